// round 16
// baseline (speedup 1.0000x reference)
#include <cuda_runtime.h>
#include <cstdint>

// Problem constants (fixed by setup_inputs)
#define NB 8
#define NH 100
#define NT 1000
#define NTS 80000   // NT * 80
#define BLK 256
#define NH2 (NH / 2)   // 50 harmonic pairs
#define NW 5           // interp columns per 256-sample window

// mod-2pi constants (R5-proven; k < 2^18)
// fusion-independent 3-term split: HI1=6.25, HI2=17*2^-9 (k*HI exact products)
#define INV2PI 0.15915494309189535f
#define MAGIC  12582912.0f                 // 1.5 * 2^23
#define NHI1 (-6.25f)
#define NHI2 (-0.033203125f)
#define C3T  (1.7817820414e-5f)            // HI1+HI2-2pi

typedef unsigned long long u64;

// ---- packed f32x2 helpers (Blackwell sm_103a) ----
__device__ __forceinline__ u64 pk2(float lo, float hi) {
    u64 r; asm("mov.b64 %0, {%1, %2};" : "=l"(r) : "f"(lo), "f"(hi)); return r;
}
__device__ __forceinline__ void upk2(float& lo, float& hi, u64 v) {
    asm("mov.b64 {%0, %1}, %2;" : "=f"(lo), "=f"(hi) : "l"(v));
}
__device__ __forceinline__ u64 add2(u64 a, u64 b) {
    u64 r; asm("add.rn.f32x2 %0, %1, %2;" : "=l"(r) : "l"(a), "l"(b)); return r;
}
__device__ __forceinline__ u64 fma2(u64 a, u64 b, u64 c) {
    u64 r; asm("fma.rn.f32x2 %0, %1, %2, %3;" : "=l"(r) : "l"(a), "l"(b), "l"(c)); return r;
}

// smem entry: one LDS.128 = two aligned u64 lane-pairs
struct __align__(16) QPair { u64 x0; u64 d; };   // (x0_h, x0_h+1), (d_h, d_h+1)

// scalar Taylor-15 odd sine, valid on |r| <= pi + 0.05 (err <= ~1e-6).
// All coefficients are immediates/const-bank: zero register footprint.
__device__ __forceinline__ float sin_poly15(float r) {
    float q = __fmul_rn(r, r);
    float t = __fmaf_rn(q, -7.64716373e-13f, 1.60590438e-10f);
    t = __fmaf_rn(q, t, -2.50521084e-8f);
    t = __fmaf_rn(q, t,  2.75573192e-6f);
    t = __fmaf_rn(q, t, -1.98412698e-4f);
    t = __fmaf_rn(q, t,  8.33333333e-3f);
    t = __fmaf_rn(q, t, -1.66666667e-1f);
    return __fmaf_rn(__fmul_rn(r, q), t, r);   // r + r*q*P(q)
}

__global__ __launch_bounds__(BLK, 7)   // reg cap 36: 7 blocks/SM, 87.5% occ
void HarmonicOscillator_kernel(
    const float* __restrict__ f0,   // [B,1,T]
    const float* __restrict__ hd,   // [B,H,T]
    const float* __restrict__ ps,   // [B,1,T]
    float* __restrict__ out)        // [B,Ts]
{
    __shared__ QPair q[NH2 * NW];

    const int s0 = blockIdx.x * BLK;
    const int b  = blockIdx.y;
    const int s  = s0 + threadIdx.x;

    const float R = (float)(999.0 / 79999.0);   // (T-1)/(Ts-1) rounded like jax f32

    // Block-uniform window start (i0 monotone; spans <=5 values over 256 samples)
    int j0 = (int)__fmul_rn((float)s0, R);
    if (j0 > NT - 2) j0 = NT - 2;

    // --- cooperative smem fill: 250 pair-entries ---
    {
        const float* hb = hd + (size_t)b * (NH * NT);
        for (int idx = threadIdx.x; idx < NH2 * NW; idx += BLK) {
            int h2 = idx / NW;
            int j  = idx - h2 * NW;
            int g0 = j0 + j;  if (g0 > NT - 1) g0 = NT - 1;
            int g1 = g0 + 1;  if (g1 > NT - 1) g1 = NT - 1;
            const float* r0 = hb + (2 * h2) * NT;
            const float* r1 = r0 + NT;
            float a0 = __ldg(r0 + g0), a1 = __ldg(r0 + g1);
            float b0 = __ldg(r1 + g0), b1 = __ldg(r1 + g1);
            q[idx].x0 = pk2(a0, b0);
            q[idx].d  = pk2(__fsub_rn(a1, a0), __fsub_rn(b1, b0));
        }
    }
    __syncthreads();

    if (s >= NTS) return;

    // --- per-thread interpolation coords (match jnp f32 rounding exactly) ---
    float sF  = (float)s;
    float pos = __fmul_rn(sF, R);
    int i0 = (int)pos;                   // pos >= 0 -> trunc == floor
    if (i0 > NT - 2) i0 = NT - 2;
    float w = __fsub_rn(pos, (float)i0);
    int li = i0 - j0;                    // 0..4

    // --- f0 / phase_shift interp: x0 + (x1-x0)*w, separate roundings ---
    const float* f0b = f0 + b * NT;
    const float* psb = ps + b * NT;
    float fa = __ldg(f0b + i0), fb = __ldg(f0b + i0 + 1);
    float f0u = __fadd_rn(fa, __fmul_rn(__fsub_rn(fb, fa), w));
    float pa = __ldg(psb + i0), pb = __ldg(psb + i0 + 1);
    float psu = __fadd_rn(pa, __fmul_rn(__fsub_rn(pb, pa), w));

    // base = fl(fl(C * f0u) * t), C = fl(2*pi/16000)
    const float C = (float)(2.0 * 3.14159265358979323846 / 16000.0);
    float base = __fmul_rn(__fmul_rn(C, f0u), sF);

    const QPair* qp = q + li;

    // packed loop-invariant operands (same count as R5: fits 30-reg budget)
    u64 psu2  = pk2(psu, psu);
    u64 w2    = pk2(w, w);
    u64 INV2  = pk2(INV2PI, INV2PI);
    u64 MG2   = pk2(MAGIC, MAGIC);
    u64 NMG2  = pk2(-MAGIC, -MAGIC);
    u64 NH1_2 = pk2(NHI1, NHI1);
    u64 NH2_2 = pk2(NHI2, NHI2);
    u64 C3_2  = pk2(C3T, C3T);

    u64 acc2 = pk2(0.0f, 0.0f);

    // Per-warp poly position: de-correlates poly iterations across warps so
    // the XU pipe never goes block-wide idle (1 in 5 pairs -> x = 0.2).
    const int ppos = ((threadIdx.x >> 5) % 5);

    // exact-integer float multiplier recurrence (keeps group loop compact)
    float hOdd = 1.0f, hEven = 2.0f;
    const QPair* qg = qp;

    #pragma unroll 2
    for (int g = 0; g < 10; ++g) {
        #pragma unroll
        for (int posi = 0; posi < 5; ++posi) {
            QPair v = qg[posi * NW];                  // one LDS.128

            // X = fl(fl(base*h) + psu) per lane -- bit-exact vs reference
            float p0 = __fmul_rn(base, hOdd);
            float p1 = __fmul_rn(base, hEven);
            u64 X2 = add2(pk2(p0, p1), psu2);

            // fusion-independent reduction mod 2*pi: r in [-pi-eps, pi+eps]
            u64 kb2 = fma2(X2, INV2, MG2);
            u64 kf2 = add2(kb2, NMG2);
            u64 r2  = fma2(kf2, NH1_2, X2);   // exact
            r2      = fma2(kf2, NH2_2, r2);   // exact
            r2      = fma2(kf2, C3_2, r2);    // ~2e-7 fused or split

            float r0, r1; upk2(r0, r1, r2);
            u64 s2;
            if (posi != ppos) {
                // MUFU pair (4 of 5): XU-pipe sine (R5 path, no ALU tax)
                s2 = pk2(__sinf(r0), __sinf(r1));
            } else {
                // poly pair (1 of 5): scalar fma-pipe Taylor-15, imm coeffs
                s2 = pk2(sin_poly15(r0), sin_poly15(r1));
            }

            acc2 = fma2(s2, fma2(v.d, w2, v.x0), acc2);

            hOdd  = __fadd_rn(hOdd, 2.0f);
            hEven = __fadd_rn(hEven, 2.0f);
        }
        qg += 5 * NW;
    }

    float a0, a1; upk2(a0, a1, acc2);
    out[(size_t)b * NTS + s] = __fadd_rn(a0, a1);
}

extern "C" void kernel_launch(void* const* d_in, const int* in_sizes, int n_in,
                              void* d_out, int out_size) {
    const float* f0 = (const float*)d_in[0];
    const float* hd = (const float*)d_in[1];
    const float* ps = (const float*)d_in[2];
    float* out = (float*)d_out;

    dim3 block(BLK);
    dim3 grid((NTS + BLK - 1) / BLK, NB);
    HarmonicOscillator_kernel<<<grid, block>>>(f0, hd, ps, out);
}

// round 17
// speedup vs baseline: 1.1323x; 1.1323x over previous
#include <cuda_runtime.h>
#include <cstdint>

// Problem constants (fixed by setup_inputs)
#define NB 8
#define NH 100
#define NT 1000
#define NTS 80000   // NT * 80
#define BLK 256
#define NH2 (NH / 2)   // 50 harmonic pairs
#define NW 5           // interp columns per 256-sample window

// mod-2pi constants (R5-proven; k < 2^18)
// fusion-independent 3-term split: HI1=6.25, HI2=17*2^-9 (k*HI exact products)
#define INV2PI 0.15915494309189535f
#define MAGIC  12582912.0f                 // 1.5 * 2^23
#define NHI1 (-6.25f)
#define NHI2 (-0.033203125f)
#define C3T  (1.7817820414e-5f)            // HI1+HI2-2pi

typedef unsigned long long u64;

// ---- packed f32x2 helpers (Blackwell sm_103a) ----
__device__ __forceinline__ u64 pk2(float lo, float hi) {
    u64 r; asm("mov.b64 %0, {%1, %2};" : "=l"(r) : "f"(lo), "f"(hi)); return r;
}
__device__ __forceinline__ void upk2(float& lo, float& hi, u64 v) {
    asm("mov.b64 {%0, %1}, %2;" : "=f"(lo), "=f"(hi) : "l"(v));
}
__device__ __forceinline__ u64 add2(u64 a, u64 b) {
    u64 r; asm("add.rn.f32x2 %0, %1, %2;" : "=l"(r) : "l"(a), "l"(b)); return r;
}
__device__ __forceinline__ u64 fma2(u64 a, u64 b, u64 c) {
    u64 r; asm("fma.rn.f32x2 %0, %1, %2, %3;" : "=l"(r) : "l"(a), "l"(b), "l"(c)); return r;
}

// smem entry: one LDS.128 = two aligned u64 lane-pairs
struct __align__(16) QPair { u64 x0; u64 d; };   // (x0_h, x0_h+1), (d_h, d_h+1)

// scalar Taylor-15 odd sine, valid on |r| <= pi + 0.05 (abs err <= ~1e-6).
// All coefficients are immediates/const-bank: zero register footprint.
__device__ __forceinline__ float sin_poly15(float r) {
    float q = __fmul_rn(r, r);
    float t = __fmaf_rn(q, -7.64716373e-13f, 1.60590438e-10f);
    t = __fmaf_rn(q, t, -2.50521084e-8f);
    t = __fmaf_rn(q, t,  2.75573192e-6f);
    t = __fmaf_rn(q, t, -1.98412698e-4f);
    t = __fmaf_rn(q, t,  8.33333333e-3f);
    t = __fmaf_rn(q, t, -1.66666667e-1f);
    return __fmaf_rn(__fmul_rn(r, q), t, r);   // r + r*q*P(q)
}

__global__ __launch_bounds__(BLK)
void HarmonicOscillator_kernel(
    const float* __restrict__ f0,   // [B,1,T]
    const float* __restrict__ hd,   // [B,H,T]
    const float* __restrict__ ps,   // [B,1,T]
    float* __restrict__ out)        // [B,Ts]
{
    __shared__ QPair q[NH2 * NW];

    const int s0 = blockIdx.x * BLK;
    const int b  = blockIdx.y;
    const int s  = s0 + threadIdx.x;

    const float R = (float)(999.0 / 79999.0);   // (T-1)/(Ts-1) rounded like jax f32

    // Block-uniform window start (i0 monotone; spans <=5 values over 256 samples)
    int j0 = (int)__fmul_rn((float)s0, R);
    if (j0 > NT - 2) j0 = NT - 2;

    // --- cooperative smem fill: 250 pair-entries ---
    {
        const float* hb = hd + (size_t)b * (NH * NT);
        for (int idx = threadIdx.x; idx < NH2 * NW; idx += BLK) {
            int h2 = idx / NW;
            int j  = idx - h2 * NW;
            int g0 = j0 + j;  if (g0 > NT - 1) g0 = NT - 1;
            int g1 = g0 + 1;  if (g1 > NT - 1) g1 = NT - 1;
            const float* r0 = hb + (2 * h2) * NT;
            const float* r1 = r0 + NT;
            float a0 = __ldg(r0 + g0), a1 = __ldg(r0 + g1);
            float b0 = __ldg(r1 + g0), b1 = __ldg(r1 + g1);
            q[idx].x0 = pk2(a0, b0);
            q[idx].d  = pk2(__fsub_rn(a1, a0), __fsub_rn(b1, b0));
        }
    }
    __syncthreads();

    if (s >= NTS) return;

    // --- per-thread interpolation coords (match jnp f32 rounding exactly) ---
    float sF  = (float)s;
    float pos = __fmul_rn(sF, R);
    int i0 = (int)pos;                   // pos >= 0 -> trunc == floor
    if (i0 > NT - 2) i0 = NT - 2;
    float w = __fsub_rn(pos, (float)i0);
    int li = i0 - j0;                    // 0..4

    // --- f0 / phase_shift interp: x0 + (x1-x0)*w, separate roundings ---
    const float* f0b = f0 + b * NT;
    const float* psb = ps + b * NT;
    float fa = __ldg(f0b + i0), fb = __ldg(f0b + i0 + 1);
    float f0u = __fadd_rn(fa, __fmul_rn(__fsub_rn(fb, fa), w));
    float pa = __ldg(psb + i0), pb = __ldg(psb + i0 + 1);
    float psu = __fadd_rn(pa, __fmul_rn(__fsub_rn(pb, pa), w));

    // base = fl(fl(C * f0u) * t), C = fl(2*pi/16000)
    const float C = (float)(2.0 * 3.14159265358979323846 / 16000.0);
    float base = __fmul_rn(__fmul_rn(C, f0u), sF);

    const QPair* qp = q + li;

    // packed loop-invariant operands (identical set to round-5 champion)
    u64 psu2  = pk2(psu, psu);
    u64 w2    = pk2(w, w);
    u64 INV2  = pk2(INV2PI, INV2PI);
    u64 MG2   = pk2(MAGIC, MAGIC);
    u64 NMG2  = pk2(-MAGIC, -MAGIC);
    u64 NH1_2 = pk2(NHI1, NHI1);
    u64 NH2_2 = pk2(NHI2, NHI2);
    u64 C3_2  = pk2(C3T, C3T);

    u64 acc2 = pk2(0.0f, 0.0f);

    // One poly group of 10 pairs per warp (wid%5): x = 0.2 offload, spatially
    // decorrelated across warps so the XU pipe never goes block-wide idle.
    const int ppos = ((threadIdx.x >> 5) % 5);

    #pragma unroll
    for (int g = 0; g < 5; ++g) {
        if (g != ppos) {
            // ===== MUFU group (10 pairs): verbatim R5 bodies, XU sine =====
            #pragma unroll
            for (int t = 0; t < 10; ++t) {
                const int h2 = g * 10 + t;               // compile-time
                QPair v = qp[h2 * NW];                   // one LDS.128

                float p0 = __fmul_rn(base, (float)(2 * h2 + 1));  // FMUL-imm
                float p1 = __fmul_rn(base, (float)(2 * h2 + 2));
                u64 X2 = add2(pk2(p0, p1), psu2);        // bit-exact ref phase

                u64 kb2 = fma2(X2, INV2, MG2);
                u64 kf2 = add2(kb2, NMG2);
                u64 r2  = fma2(kf2, NH1_2, X2);   // exact
                r2      = fma2(kf2, NH2_2, r2);   // exact
                r2      = fma2(kf2, C3_2, r2);    // ~2e-7

                float r0, r1; upk2(r0, r1, r2);
                u64 s2 = pk2(__sinf(r0), __sinf(r1));    // 2x MUFU.SIN (XU)

                acc2 = fma2(s2, fma2(v.d, w2, v.x0), acc2);
            }
        } else {
            // ===== poly group (10 pairs): same reduction, fma-pipe sine =====
            #pragma unroll
            for (int t = 0; t < 10; ++t) {
                const int h2 = g * 10 + t;               // compile-time
                QPair v = qp[h2 * NW];                   // one LDS.128

                float p0 = __fmul_rn(base, (float)(2 * h2 + 1));  // FMUL-imm
                float p1 = __fmul_rn(base, (float)(2 * h2 + 2));
                u64 X2 = add2(pk2(p0, p1), psu2);

                u64 kb2 = fma2(X2, INV2, MG2);
                u64 kf2 = add2(kb2, NMG2);
                u64 r2  = fma2(kf2, NH1_2, X2);   // exact
                r2      = fma2(kf2, NH2_2, r2);   // exact
                r2      = fma2(kf2, C3_2, r2);    // ~2e-7; r in [-pi-eps, pi+eps]

                float r0, r1; upk2(r0, r1, r2);
                u64 s2 = pk2(sin_poly15(r0), sin_poly15(r1));   // fma pipe

                acc2 = fma2(s2, fma2(v.d, w2, v.x0), acc2);
            }
        }
    }

    float a0, a1; upk2(a0, a1, acc2);
    out[(size_t)b * NTS + s] = __fadd_rn(a0, a1);
}

extern "C" void kernel_launch(void* const* d_in, const int* in_sizes, int n_in,
                              void* d_out, int out_size) {
    const float* f0 = (const float*)d_in[0];
    const float* hd = (const float*)d_in[1];
    const float* ps = (const float*)d_in[2];
    float* out = (float*)d_out;

    dim3 block(BLK);
    dim3 grid((NTS + BLK - 1) / BLK, NB);
    HarmonicOscillator_kernel<<<grid, block>>>(f0, hd, ps, out);
}